// round 1
// baseline (speedup 1.0000x reference)
#include <cuda_runtime.h>
#include <cuda_bf16.h>

#define E_ 32
#define T_ 2048
#define H_ 1024
#define I_ 512
#define K_ 4
#define P_ (T_ * K_)   // 8192 (token, k) pairs

#define TM 64
#define TN 64
#define TKK 16
#define NTHREADS 256

// ---------------- device scratch (no allocations allowed) ----------------
__device__ int   g_counts[E_];
__device__ int   g_segoff[E_ + 1];
__device__ int   g_pair_tok[P_];
__device__ float g_pair_w[P_];
__device__ float g_hbuf[(size_t)P_ * I_];   // 16 MB intermediate h

// ---------------- routing ----------------
__global__ void zero_kernel(float* __restrict__ out) {
    int i = blockIdx.x * blockDim.x + threadIdx.x;
    if (i < T_ * H_) out[i] = 0.0f;
    if (i < E_) g_counts[i] = 0;
}

__global__ void count_kernel(const int* __restrict__ idx) {
    int p = blockIdx.x * blockDim.x + threadIdx.x;
    if (p < P_) atomicAdd(&g_counts[idx[p]], 1);
}

__global__ void scan_kernel() {
    if (threadIdx.x == 0) {
        int s = 0;
        g_segoff[0] = 0;
        for (int e = 0; e < E_; e++) { s += g_counts[e]; g_segoff[e + 1] = s; }
    }
}

// Stable (deterministic) scatter: block e scans all pairs in index order.
__global__ void scatter_kernel(const int* __restrict__ idx, const float* __restrict__ w) {
    int e = blockIdx.x;
    __shared__ int s_scan[NTHREADS];
    int base = g_segoff[e];
    for (int chunk = 0; chunk < P_; chunk += NTHREADS) {
        int p = chunk + threadIdx.x;          // P_ is a multiple of NTHREADS
        int m = (idx[p] == e) ? 1 : 0;
        s_scan[threadIdx.x] = m;
        __syncthreads();
        // Hillis-Steele inclusive scan
        for (int off = 1; off < NTHREADS; off <<= 1) {
            int v = (threadIdx.x >= off) ? s_scan[threadIdx.x - off] : 0;
            __syncthreads();
            s_scan[threadIdx.x] += v;
            __syncthreads();
        }
        int incl  = s_scan[threadIdx.x];
        int total = s_scan[NTHREADS - 1];
        if (m) {
            int pos = base + incl - 1;
            g_pair_tok[pos] = p >> 2;         // token = p / K
            g_pair_w[pos]   = w[p];
        }
        base += total;
        __syncthreads();
    }
}

// ---------------- GEMM 1: h = silu(x Wg^T) * (x Wu^T) ----------------
// grid: (E, I/TN, maxMtiles); NT gemm, K = H contiguous on both operands.
__global__ __launch_bounds__(NTHREADS)
void gateup_kernel(const float* __restrict__ hidden, const float* __restrict__ gup) {
    int e = blockIdx.x;
    int seg_s = g_segoff[e], seg_e = g_segoff[e + 1];
    int m0 = seg_s + blockIdx.z * TM;
    if (m0 >= seg_e) return;
    int mcnt = min(TM, seg_e - m0);
    int n0 = blockIdx.y * TN;

    __shared__ float sA [TKK][TM];
    __shared__ float sBg[TKK][TN];
    __shared__ float sBu[TKK][TN];

    int tid = threadIdx.x;
    int tx = tid & 15, ty = tid >> 4;

    // per-thread A-load descriptors (4 elements each)
    const float* aptr[4];
    #pragma unroll
    for (int l = 0; l < 4; l++) {
        int id  = tid + l * NTHREADS;
        int row = id >> 4;
        int tok = (row < mcnt) ? g_pair_tok[m0 + row] : -1;
        aptr[l] = (tok >= 0) ? hidden + (size_t)tok * H_ : nullptr;
    }
    const float* bbase = gup + (size_t)e * 2 * I_ * H_;

    float accg[4][4] = {}, accu[4][4] = {};

    for (int k0 = 0; k0 < H_; k0 += TKK) {
        #pragma unroll
        for (int l = 0; l < 4; l++) {
            int id  = tid + l * NTHREADS;
            int row = id >> 4, kk = id & 15;
            sA [kk][row] = aptr[l] ? aptr[l][k0 + kk] : 0.0f;
            sBg[kk][row] = bbase[(size_t)(n0 + row)       * H_ + k0 + kk];
            sBu[kk][row] = bbase[(size_t)(I_ + n0 + row)  * H_ + k0 + kk];
        }
        __syncthreads();
        #pragma unroll
        for (int kk = 0; kk < TKK; kk++) {
            float4 av = *(const float4*)&sA [kk][ty * 4];
            float4 gv = *(const float4*)&sBg[kk][tx * 4];
            float4 uv = *(const float4*)&sBu[kk][tx * 4];
            float a[4] = {av.x, av.y, av.z, av.w};
            float g[4] = {gv.x, gv.y, gv.z, gv.w};
            float u[4] = {uv.x, uv.y, uv.z, uv.w};
            #pragma unroll
            for (int i = 0; i < 4; i++)
                #pragma unroll
                for (int j = 0; j < 4; j++) {
                    accg[i][j] += a[i] * g[j];
                    accu[i][j] += a[i] * u[j];
                }
        }
        __syncthreads();
    }

    #pragma unroll
    for (int i = 0; i < 4; i++) {
        int r = ty * 4 + i;
        if (r < mcnt) {
            float* hrow = g_hbuf + (size_t)(m0 + r) * I_ + n0;
            #pragma unroll
            for (int j = 0; j < 4; j++) {
                float g = accg[i][j];
                float h = g * (1.0f / (1.0f + __expf(-g))) * accu[i][j];
                hrow[tx * 4 + j] = h;
            }
        }
    }
}

// ---------------- GEMM 2: out[tok] += w * (h Wd^T) ----------------
// grid: (E, H/TN, maxMtiles); NT gemm, K = I contiguous on both operands.
__global__ __launch_bounds__(NTHREADS)
void down_kernel(const float* __restrict__ down, float* __restrict__ out) {
    int e = blockIdx.x;
    int seg_s = g_segoff[e], seg_e = g_segoff[e + 1];
    int m0 = seg_s + blockIdx.z * TM;
    if (m0 >= seg_e) return;
    int mcnt = min(TM, seg_e - m0);
    int n0 = blockIdx.y * TN;

    __shared__ float sA[TKK][TM];
    __shared__ float sB[TKK][TN];

    int tid = threadIdx.x;
    int tx = tid & 15, ty = tid >> 4;
    const float* dbase = down + (size_t)e * H_ * I_;

    float acc[4][4] = {};

    for (int k0 = 0; k0 < I_; k0 += TKK) {
        #pragma unroll
        for (int l = 0; l < 4; l++) {
            int id  = tid + l * NTHREADS;
            int row = id >> 4, kk = id & 15;
            sA[kk][row] = (row < mcnt) ? g_hbuf[(size_t)(m0 + row) * I_ + k0 + kk] : 0.0f;
            sB[kk][row] = dbase[(size_t)(n0 + row) * I_ + k0 + kk];
        }
        __syncthreads();
        #pragma unroll
        for (int kk = 0; kk < TKK; kk++) {
            float4 av = *(const float4*)&sA[kk][ty * 4];
            float4 bv = *(const float4*)&sB[kk][tx * 4];
            float a[4] = {av.x, av.y, av.z, av.w};
            float b[4] = {bv.x, bv.y, bv.z, bv.w};
            #pragma unroll
            for (int i = 0; i < 4; i++)
                #pragma unroll
                for (int j = 0; j < 4; j++)
                    acc[i][j] += a[i] * b[j];
        }
        __syncthreads();
    }

    #pragma unroll
    for (int i = 0; i < 4; i++) {
        int r = ty * 4 + i;
        if (r < mcnt) {
            int   tok = g_pair_tok[m0 + r];
            float w   = g_pair_w[m0 + r];
            float* orow = out + (size_t)tok * H_ + n0;
            #pragma unroll
            for (int j = 0; j < 4; j++)
                atomicAdd(&orow[tx * 4 + j], w * acc[i][j]);
        }
    }
}

// ---------------- launch ----------------
extern "C" void kernel_launch(void* const* d_in, const int* in_sizes, int n_in,
                              void* d_out, int out_size) {
    const float* hidden = (const float*)d_in[0];
    const int*   idx    = (const int*)  d_in[1];
    const float* wts    = (const float*)d_in[2];
    const float* gup    = (const float*)d_in[3];
    const float* down   = (const float*)d_in[4];
    float* out = (float*)d_out;

    zero_kernel<<<(T_ * H_ + 255) / 256, 256>>>(out);
    count_kernel<<<P_ / 256, 256>>>(idx);
    scan_kernel<<<1, 32>>>();
    scatter_kernel<<<E_, NTHREADS>>>(idx, wts);

    dim3 g1(E_, I_ / TN, (P_ + TM - 1) / TM);
    gateup_kernel<<<g1, NTHREADS>>>(hidden, gup);

    dim3 g2(E_, H_ / TN, (P_ + TM - 1) / TM);
    down_kernel<<<g2, NTHREADS>>>(down, out);
}

// round 6
// speedup vs baseline: 3.6670x; 3.6670x over previous
#include <cuda_runtime.h>
#include <cuda_bf16.h>
#include <cstdint>
#include <cstddef>

#define E_ 32
#define T_ 2048
#define H_ 1024
#define I_ 512
#define K_ 4
#define P_ (T_ * K_)   // 8192 (token,k) pairs

// ---------------- device scratch ----------------
__device__ int   g_counts[E_];
__device__ int   g_segoff[E_ + 1];
__device__ int   g_pair_tok[P_];   // sorted pos -> token
__device__ int   g_inv[P_];        // pair p -> sorted pos
__device__ float g_gu[(size_t)P_ * 2 * I_];   // 32 MB: gate_up output, reused as down output
__device__ float g_hbuf[(size_t)P_ * I_];     // 16 MB: silu(gate)*up

// ---------------- routing ----------------
__global__ void zero_counts_kernel() {
    if (threadIdx.x < E_) g_counts[threadIdx.x] = 0;
}

__global__ void count_kernel(const int* __restrict__ idx) {
    int p = blockIdx.x * blockDim.x + threadIdx.x;
    if (p < P_) atomicAdd(&g_counts[idx[p]], 1);
}

__global__ void scan_kernel() {
    if (threadIdx.x == 0) {
        int s = 0;
        g_segoff[0] = 0;
        for (int e = 0; e < E_; e++) { s += g_counts[e]; g_segoff[e + 1] = s; }
    }
}

// Stable scatter via warp-ballot scan. Block e processes all pairs in index order.
__global__ void scatter_kernel(const int* __restrict__ idx) {
    int e = blockIdx.x;
    int tid = threadIdx.x, lane = tid & 31, wid = tid >> 5;
    __shared__ int wsum[8];
    __shared__ int sbase;
    if (tid == 0) sbase = g_segoff[e];
    __syncthreads();
    for (int c = 0; c < P_; c += 256) {
        int p = c + tid;
        bool m = (idx[p] == e);
        unsigned bal = __ballot_sync(0xffffffffu, m);
        int wcnt = __popc(bal);
        int lpre = __popc(bal & ((1u << lane) - 1u));
        if (lane == 0) wsum[wid] = wcnt;
        __syncthreads();
        int woff = 0, tot = 0;
        #pragma unroll
        for (int w = 0; w < 8; w++) { int v = wsum[w]; if (w < wid) woff += v; tot += v; }
        if (m) {
            int pos = sbase + woff + lpre;
            g_pair_tok[pos] = p >> 2;
            g_inv[p] = pos;
        }
        __syncthreads();
        if (tid == 0) sbase += tot;
        __syncthreads();
    }
}

// ---------------- tf32 helpers ----------------
__device__ __forceinline__ uint32_t f2tf32(float f) {
    uint32_t u;
    asm("cvt.rna.tf32.f32 %0, %1;" : "=r"(u) : "f"(f));
    return u;
}

__device__ __forceinline__ uint4 ldcvt4(const float* p) {
    float4 v = *(const float4*)p;
    uint4 u;
    u.x = f2tf32(v.x); u.y = f2tf32(v.y); u.z = f2tf32(v.z); u.w = f2tf32(v.w);
    return u;
}

__device__ __forceinline__ void mma_tf32(float c[4], uint32_t a0, uint32_t a1, uint32_t a2, uint32_t a3,
                                         uint32_t b0, uint32_t b1) {
    asm("mma.sync.aligned.m16n8k8.row.col.f32.tf32.tf32.f32 "
        "{%0,%1,%2,%3}, {%4,%5,%6,%7}, {%8,%9}, {%0,%1,%2,%3};"
        : "+f"(c[0]), "+f"(c[1]), "+f"(c[2]), "+f"(c[3])
        : "r"(a0), "r"(a1), "r"(a2), "r"(a3), "r"(b0), "r"(b1));
}

// ---------------- grouped NT GEMM: C[m, n0:n0+128] = A[m,:] * B[n,:]^T ----------------
// BM=128, BN=128, BK=16, 256 threads (8 warps as 4x2), warp tile 32x64,
// per-warp 2 (m16) x 8 (n8) mma tiles. Double-buffered smem, pad-20 rows.
template<int KDIM, bool GATHER>
__global__ __launch_bounds__(256, 2)
void gemm_kernel(const float* __restrict__ Abase,
                 const float* __restrict__ Ball, size_t bstride,
                 float* __restrict__ C) {
    int e = blockIdx.z;
    int seg_s = g_segoff[e], seg_e = g_segoff[e + 1];
    int m0 = seg_s + blockIdx.x * 128;
    if (m0 >= seg_e) return;
    int n0 = blockIdx.y * 128;
    int mcnt = min(128, seg_e - m0);

    int tid = threadIdx.x, lane = tid & 31, wid = tid >> 5;
    int wm = (wid & 3) * 32;       // warp m offset
    int wn = (wid >> 2) * 64;      // warp n offset

    __shared__ uint32_t sA[2][128][20];
    __shared__ uint32_t sB[2][128][20];

    // load assignment: thread covers float4 (row r0, colf) and (row r1, colf)
    int r0 = tid >> 2, r1 = r0 + 64;
    int cf = (tid & 3) * 4;

    const float* a0p;
    const float* a1p;
    if (GATHER) {
        int g0 = min(m0 + r0, P_ - 1);
        int g1 = min(m0 + r1, P_ - 1);
        a0p = Abase + (size_t)g_pair_tok[g0] * KDIM + cf;
        a1p = Abase + (size_t)g_pair_tok[g1] * KDIM + cf;
    } else {
        a0p = Abase + (size_t)min(m0 + r0, P_ - 1) * KDIM + cf;
        a1p = Abase + (size_t)min(m0 + r1, P_ - 1) * KDIM + cf;
    }
    const float* Bb = Ball + (size_t)e * bstride;
    const float* b0p = Bb + (size_t)(n0 + r0) * KDIM + cf;
    const float* b1p = Bb + (size_t)(n0 + r1) * KDIM + cf;

    float acc[2][8][4];
    #pragma unroll
    for (int i = 0; i < 2; i++)
        #pragma unroll
        for (int j = 0; j < 8; j++)
            #pragma unroll
            for (int q = 0; q < 4; q++) acc[i][j][q] = 0.0f;

    // prologue: stage tile 0
    uint4 ra0 = ldcvt4(a0p), ra1 = ldcvt4(a1p);
    uint4 rb0 = ldcvt4(b0p), rb1 = ldcvt4(b1p);
    *(uint4*)&sA[0][r0][cf] = ra0;
    *(uint4*)&sA[0][r1][cf] = ra1;
    *(uint4*)&sB[0][r0][cf] = rb0;
    *(uint4*)&sB[0][r1][cf] = rb1;
    __syncthreads();

    const int NKB = KDIM / 16;
    for (int kb = 0; kb < NKB; kb++) {
        int cur = kb & 1, nxt = cur ^ 1;
        if (kb + 1 < NKB) {
            int ko = (kb + 1) * 16;
            ra0 = ldcvt4(a0p + ko); ra1 = ldcvt4(a1p + ko);
            rb0 = ldcvt4(b0p + ko); rb1 = ldcvt4(b1p + ko);
        }

        #pragma unroll
        for (int ks = 0; ks < 2; ks++) {
            int k0 = ks * 8;
            int kc = k0 + (lane & 3);
            uint32_t af[2][4];
            #pragma unroll
            for (int mi = 0; mi < 2; mi++) {
                int rm = wm + mi * 16 + (lane >> 2);
                af[mi][0] = sA[cur][rm][kc];
                af[mi][1] = sA[cur][rm + 8][kc];
                af[mi][2] = sA[cur][rm][kc + 4];
                af[mi][3] = sA[cur][rm + 8][kc + 4];
            }
            #pragma unroll
            for (int j = 0; j < 8; j++) {
                int rn = wn + 8 * j + (lane >> 2);
                uint32_t bf0 = sB[cur][rn][kc];
                uint32_t bf1 = sB[cur][rn][kc + 4];
                mma_tf32(acc[0][j], af[0][0], af[0][1], af[0][2], af[0][3], bf0, bf1);
                mma_tf32(acc[1][j], af[1][0], af[1][1], af[1][2], af[1][3], bf0, bf1);
            }
        }

        if (kb + 1 < NKB) {
            *(uint4*)&sA[nxt][r0][cf] = ra0;
            *(uint4*)&sA[nxt][r1][cf] = ra1;
            *(uint4*)&sB[nxt][r0][cf] = rb0;
            *(uint4*)&sB[nxt][r1][cf] = rb1;
            __syncthreads();
        }
    }

    // epilogue: C has 2*I_ = 1024 columns for both gemms
    #pragma unroll
    for (int mi = 0; mi < 2; mi++) {
        int rbase = wm + mi * 16 + (lane >> 2);
        #pragma unroll
        for (int j = 0; j < 8; j++) {
            int col = n0 + wn + 8 * j + (lane & 3) * 2;
            if (rbase < mcnt) {
                float2 v = make_float2(acc[mi][j][0], acc[mi][j][1]);
                *(float2*)&C[(size_t)(m0 + rbase) * 1024 + col] = v;
            }
            if (rbase + 8 < mcnt) {
                float2 v = make_float2(acc[mi][j][2], acc[mi][j][3]);
                *(float2*)&C[(size_t)(m0 + rbase + 8) * 1024 + col] = v;
            }
        }
    }
}

// ---------------- silu: h = silu(gate) * up ----------------
__global__ void silu_kernel() {
    int idx = blockIdx.x * blockDim.x + threadIdx.x;   // over P_ * 128 float4
    if (idx >= P_ * (I_ / 4)) return;
    int p = idx >> 7, i4 = idx & 127;
    const float4* gu4 = (const float4*)g_gu;
    float4 g = gu4[(size_t)p * 256 + i4];
    float4 u = gu4[(size_t)p * 256 + 128 + i4];
    float4 h;
    h.x = g.x * (1.0f / (1.0f + __expf(-g.x))) * u.x;
    h.y = g.y * (1.0f / (1.0f + __expf(-g.y))) * u.y;
    h.z = g.z * (1.0f / (1.0f + __expf(-g.z))) * u.z;
    h.w = g.w * (1.0f / (1.0f + __expf(-g.w))) * u.w;
    ((float4*)g_hbuf)[(size_t)p * 128 + i4] = h;
}

// ---------------- combine: out[t] = sum_k w[t,k] * dout[inv[t*K+k]] ----------------
__global__ void combine_kernel(const float* __restrict__ wts, float* __restrict__ out) {
    int idx = blockIdx.x * blockDim.x + threadIdx.x;   // over T_ * 256 float4
    if (idx >= T_ * (H_ / 4)) return;
    int t = idx >> 8, c = idx & 255;
    const float4* dout4 = (const float4*)g_gu;
    float4 acc = make_float4(0.f, 0.f, 0.f, 0.f);
    #pragma unroll
    for (int k = 0; k < K_; k++) {
        int p = t * K_ + k;
        int pos = g_inv[p];
        float w = wts[p];
        float4 v = dout4[(size_t)pos * 256 + c];
        acc.x += w * v.x; acc.y += w * v.y; acc.z += w * v.z; acc.w += w * v.w;
    }
    ((float4*)out)[idx] = acc;
}

// ---------------- launch ----------------
extern "C" void kernel_launch(void* const* d_in, const int* in_sizes, int n_in,
                              void* d_out, int out_size) {
    const float* hidden = (const float*)d_in[0];
    const int*   idx    = (const int*)  d_in[1];
    const float* wts    = (const float*)d_in[2];
    const float* gup    = (const float*)d_in[3];
    const float* down   = (const float*)d_in[4];
    float* out = (float*)d_out;

    float* gu   = nullptr; cudaGetSymbolAddress((void**)&gu,   g_gu);
    float* hbuf = nullptr; cudaGetSymbolAddress((void**)&hbuf, g_hbuf);

    zero_counts_kernel<<<1, 32>>>();
    count_kernel<<<P_ / 256, 256>>>(idx);
    scan_kernel<<<1, 32>>>();
    scatter_kernel<<<E_, 256>>>(idx);

    // GEMM1: gu[p, 0:1024] = hidden[tok(p), :] @ gup[e]^T   (K = H = 1024)
    dim3 g1(P_ / 128, 1024 / 128, E_);
    gemm_kernel<H_, true><<<g1, 256>>>(hidden, gup, (size_t)2 * I_ * H_, gu);

    silu_kernel<<<(P_ * (I_ / 4) + 255) / 256, 256>>>();

    // GEMM2: dout[p, 0:1024] = h[p, :] @ down[e]^T   (K = I = 512), reuse g_gu as dout
    dim3 g2(P_ / 128, 1024 / 128, E_);
    gemm_kernel<I_, false><<<g2, 256>>>(hbuf, down, (size_t)H_ * I_, gu);

    combine_kernel<<<(T_ * (H_ / 4) + 255) / 256, 256>>>(wts, out);
}